// round 13
// baseline (speedup 1.0000x reference)
#include <cuda_runtime.h>
#include <math.h>

#define NN 10000
#define NE 160000

// ---------------- scratch (static device globals; no allocation) ----------------
__device__ float g_US[NE * 4];           // sorted unit vectors (float4 per CSR slot)
__device__ int   g_srcs[NE];             // sorted src node per CSR slot
__device__ int   g_cnt[NN];              // INVARIANT: zero at kernel_launch entry/exit
__device__ int   g_off[NN + 1];
__device__ int   g_cur[NN];
__device__ float g_H0[NN * 32];          // (N,C)
__device__ float g_H1[NN * 96];          // (N, d-major: d*32 + ch)
__device__ float g_H2[NN * 288];         // (N, d-major: d*32 + ch)
__device__ float g_ACC[NE * 96];         // per-CSR-slot acc (k index)
__device__ float g_accvec[96];           // layer-0 constant acc vector

// ---------------- packed f32x2 helpers ----------------
__device__ __forceinline__ unsigned long long pack2(float x, float y) {
    unsigned long long r; asm("mov.b64 %0, {%1,%2};" : "=l"(r) : "f"(x), "f"(y)); return r;
}
__device__ __forceinline__ void unpack2(unsigned long long v, float& x, float& y) {
    asm("mov.b64 {%0,%1}, %2;" : "=f"(x), "=f"(y) : "l"(v));
}
__device__ __forceinline__ unsigned long long fma2(unsigned long long a, unsigned long long b,
                                                   unsigned long long c) {
    unsigned long long d;
    asm("fma.rn.f32x2 %0, %1, %2, %3;" : "=l"(d) : "l"(a), "l"(b), "l"(c));
    return d;
}

// Stage a 32x32 weight matrix (1024 contiguous floats) into shared, coalesced.
// Evict-first global loads: weights are read exactly once, keep L2 for H/ACC.
// ww layout: row r at ww[r*33 .. r*33+31] (stride 33 => conflict-free STS & LDS).
__device__ __forceinline__ void stage_w(const float* __restrict__ g, float* ww, int lane) {
#pragma unroll
    for (int q = 0; q < 8; q++) {
        float4 v = __ldcs(((const float4*)g) + q * 32 + lane);
        int r = q * 4 + (lane >> 3);
        float* p = ww + r * 33 + (lane & 7) * 4;
        p[0] = v.x; p[1] = v.y; p[2] = v.z; p[3] = v.w;
    }
}

// ---------------- init: embed atoms, dst histogram, layer-0 accvec ----------------
__global__ void k_init(const float* __restrict__ emb, const int* __restrict__ atoms,
                       const float* __restrict__ W_ab, const int* __restrict__ ei) {
    int t = blockIdx.x * 256 + threadIdx.x;
    if (t < NN * 32) g_H0[t] = emb[atoms[t >> 5] * 32 + (t & 31)];
    if (t < NE)      atomicAdd(&g_cnt[ei[NE + t]], 1);
    if (t < 96) {
        int c = t >> 5, j = t & 31;
        const float* wp = W_ab + (c * 3) * 1024 + j * 32;
        float s = 0.f;
#pragma unroll
        for (int k = 0; k < 32; k++) s += wp[k] * emb[k];
        g_accvec[t] = s;
    }
}

// ---------------- single-block exclusive scan; re-zeroes g_cnt ----------------
__global__ void k_scan() {
    __shared__ int sh[1024];
    int t = threadIdx.x;
    const int PER = 10;
    int base = t * PER;
    int loc[PER];
    int s = 0;
#pragma unroll
    for (int i = 0; i < PER; i++) {
        int idx = base + i;
        int v = (idx < NN) ? g_cnt[idx] : 0;
        if (idx < NN) g_cnt[idx] = 0;
        loc[i] = s;
        s += v;
    }
    sh[t] = s;
    __syncthreads();
    for (int off = 1; off < 1024; off <<= 1) {
        int v = (t >= off) ? sh[t - off] : 0;
        __syncthreads();
        sh[t] += v;
        __syncthreads();
    }
    int excl = sh[t] - s;
#pragma unroll
    for (int i = 0; i < PER; i++) {
        int idx = base + i;
        if (idx < NN) { g_off[idx] = excl + loc[i]; g_cur[idx] = excl + loc[i]; }
    }
    if (t == 1023) g_off[NN] = sh[1023];
}

// ---------------- geometry + scatter into CSR order ----------------
__global__ void k_fill(const int* __restrict__ ei, const float* __restrict__ pos) {
    int e = blockIdx.x * 256 + threadIdx.x;
    if (e >= NE) return;
    int s = ei[e], d = ei[NE + e];
    float rx = pos[d * 3 + 0] - pos[s * 3 + 0];
    float ry = pos[d * 3 + 1] - pos[s * 3 + 1];
    float rz = pos[d * 3 + 2] - pos[s * 3 + 2];
    float nrm = sqrtf(rx * rx + ry * ry + rz * rz);
    float inv = 1.0f / (nrm + 1e-9f);
    int p = atomicAdd(&g_cur[d], 1);
    g_srcs[p] = s;
    ((float4*)g_US)[p] = make_float4(rx * inv, ry * inv, rz * inv, 0.f);
}

// ---------------- layer-0 fused gather+update: warp per (node, c) ----------------
// node-major warp mapping: node = wg/3, c = wg%3.
// dyn smem: 8 * 1056 * 4 = 33792 B.
__global__ __launch_bounds__(256) void k_upd0(const float* __restrict__ ws_w,
                                              const float* __restrict__ cwg,
                                              const float* __restrict__ mwg) {
    extern __shared__ float dsm[];
    __shared__ float FS[8][32];
    __shared__ float HS[8][32];
    int warp = threadIdx.x >> 5, lane = threadIdx.x & 31;
    float* ww = dsm + warp * 1056;
    int wg = blockIdx.x * 8 + warp;
    int node = wg / 3;
    int c = wg - node * 3;
    int beg = g_off[node], end = g_off[node + 1];
    float cnt = (float)(end - beg);
    float s0 = g_accvec[lane] * cnt;
    float s0q = s0 * s0;
    const float* ws = ws_w + lane;                // l = 0
    size_t mbase = ((size_t)c * NN + node) * 1024;
    const float* wrow = ww + lane * 33;

    if (c == 0) {
        stage_w(mwg + mbase, ww, lane);
        float f0 = ws[0] + ws[32] * s0 + ws[64] * s0q;
        FS[warp][lane] = f0 * s0;                 // M0
        HS[warp][lane] = g_H0[node * 32 + lane];
        __syncwarp();
        float o = 0.f;
#pragma unroll
        for (int j = 0; j < 32; j++) o += wrow[j] * FS[warp][j];
        __syncwarp();
        stage_w(cwg + mbase, ww, lane);
        __syncwarp();
#pragma unroll
        for (int j = 0; j < 32; j++) o += wrow[j] * HS[warp][j];
        g_H0[node * 32 + lane] = o;
    } else if (c == 1) {
        stage_w(mwg + mbase, ww, lane);
        float su0 = 0, su1 = 0, su2 = 0;
        for (int idx = beg + lane; idx < end; idx += 32) {
            float4 u = ((const float4*)g_US)[idx];
            su0 += u.x; su1 += u.y; su2 += u.z;
        }
#pragma unroll
        for (int off = 16; off; off >>= 1) {
            su0 += __shfl_xor_sync(~0u, su0, off);
            su1 += __shfl_xor_sync(~0u, su1, off);
            su2 += __shfl_xor_sync(~0u, su2, off);
        }
        float f1 = ws[96] + ws[128] * s0 + ws[160] * s0q;
        FS[warp][lane] = f1 * g_accvec[32 + lane];
        __syncwarp();
        float t = 0.f;
#pragma unroll
        for (int j = 0; j < 32; j++) t += wrow[j] * FS[warp][j];
        __syncwarp();
        float* op = g_H1 + node * 96;
        op[lane] = su0 * t; op[32 + lane] = su1 * t; op[64 + lane] = su2 * t;
    } else {
        stage_w(mwg + mbase, ww, lane);
        float s00 = 0, s01 = 0, s02 = 0, s11 = 0, s12 = 0, s22 = 0;
        for (int idx = beg + lane; idx < end; idx += 32) {
            float4 u = ((const float4*)g_US)[idx];
            s00 += u.x * u.x; s01 += u.x * u.y; s02 += u.x * u.z;
            s11 += u.y * u.y; s12 += u.y * u.z; s22 += u.z * u.z;
        }
#pragma unroll
        for (int off = 16; off; off >>= 1) {
            s00 += __shfl_xor_sync(~0u, s00, off);
            s01 += __shfl_xor_sync(~0u, s01, off);
            s02 += __shfl_xor_sync(~0u, s02, off);
            s11 += __shfl_xor_sync(~0u, s11, off);
            s12 += __shfl_xor_sync(~0u, s12, off);
            s22 += __shfl_xor_sync(~0u, s22, off);
        }
        float f2 = ws[192] + ws[224] * s0 + ws[256] * s0q;
        FS[warp][lane] = f2 * g_accvec[64 + lane];
        __syncwarp();
        float t = 0.f;
#pragma unroll
        for (int j = 0; j < 32; j++) t += wrow[j] * FS[warp][j];
        __syncwarp();
        float* op = g_H2 + node * 288;
        op[lane]       = s00 * t; op[32 + lane]  = s01 * t; op[64 + lane]  = s02 * t;
        op[96 + lane]  = s01 * t; op[128 + lane] = s11 * t; op[160 + lane] = s12 * t;
        op[192 + lane] = s02 * t; op[224 + lane] = s12 * t; op[256 + lane] = s22 * t;
    }
}

// ---------------- layer-1 edge kernel: fused S-build + (96x96)@(96xE) GEMM -------
// 256 threads / 128 CSR slots; thread tile 6k x 8e (mg in [0,16), ng in [0,16)).
// Per-rank W staging (12 KB) so dyn smem = 50688 + 12288 = 62976 B -> 3 blocks/SM.
__global__ __launch_bounds__(256, 3) void k_edge(const float* __restrict__ W_ab) {
    extern __shared__ float sm[];
    float* Ss = sm;            // [a*4224 + e_loc*33 + j]
    float* Wt = sm + 12672;    // current a-chunk: [j*96 + mg*6 + kk]
    int tid = threadIdx.x;
    int warp = tid >> 5, lane = tid & 31;
    int mg = tid & 15;
    int ng = tid >> 4;
    int e_base = blockIdx.x * 128;

#pragma unroll 4
    for (int t2 = 0; t2 < 16; t2++) {
        int e_loc = warp * 16 + t2;
        int idx = e_base + e_loc;
        int src = g_srcs[idx];
        float4 u = ((const float4*)g_US)[idx];
        float s0 = g_H0[src * 32 + lane];
        const float* h1 = g_H1 + src * 96;
        float s1 = h1[lane] * u.x + h1[32 + lane] * u.y + h1[64 + lane] * u.z;
        const float* h2 = g_H2 + src * 288;
        float s2 = u.x * (h2[lane] * u.x + h2[32 + lane] * u.y + h2[64 + lane] * u.z)
                 + u.y * (h2[96 + lane] * u.x + h2[128 + lane] * u.y + h2[160 + lane] * u.z)
                 + u.z * (h2[192 + lane] * u.x + h2[224 + lane] * u.y + h2[256 + lane] * u.z);
        Ss[e_loc * 33 + lane] = s0;
        Ss[4224 + e_loc * 33 + lane] = s1;
        Ss[8448 + e_loc * 33 + lane] = s2;
    }

    unsigned long long acc2[3][8];
#pragma unroll
    for (int p = 0; p < 3; p++)
#pragma unroll
        for (int ee = 0; ee < 8; ee++) acc2[p][ee] = 0ull;

#pragma unroll
    for (int a = 0; a < 3; a++) {
        __syncthreads();   // Ss ready (a=0) / all warps done reading prior Wt
        for (int t = tid; t < 3072; t += 256) {
            int j = t / 96, r = t - j * 96;
            int mgi = r / 6, kki = r - mgi * 6;
            int k = mgi + 16 * kki;
            Wt[t] = __ldcs(&W_ab[((3 + (k >> 5)) * 3 + a) * 1024 + (k & 31) * 32 + j]);
        }
        __syncthreads();
        const float* Sa = Ss + a * 4224;
#pragma unroll 8
        for (int j = 0; j < 32; j++) {
            const unsigned long long* wp =
                (const unsigned long long*)&Wt[j * 96 + mg * 6];
            unsigned long long w0 = wp[0], w1 = wp[1], w2 = wp[2];
            unsigned long long s2v[8];
#pragma unroll
            for (int ee = 0; ee < 8; ee++) {
                float s = Sa[(ng + 16 * ee) * 33 + j];
                s2v[ee] = pack2(s, s);
            }
#pragma unroll
            for (int ee = 0; ee < 8; ee++) {
                acc2[0][ee] = fma2(w0, s2v[ee], acc2[0][ee]);
                acc2[1][ee] = fma2(w1, s2v[ee], acc2[1][ee]);
                acc2[2][ee] = fma2(w2, s2v[ee], acc2[2][ee]);
            }
        }
    }
#pragma unroll
    for (int ee = 0; ee < 8; ee++) {
        int idx = e_base + ng + 16 * ee;
        float* op = g_ACC + (size_t)idx * 96 + mg;
#pragma unroll
        for (int p = 0; p < 3; p++) {
            float lo, hi;
            unpack2(acc2[p][ee], lo, hi);
            op[16 * (2 * p)]     = lo;
            op[16 * (2 * p + 1)] = hi;
        }
    }
}

// ---------------- layer-1 fused gather+update: warp per (node, c) ----------------
// Gather at entry (overlaps cw staging); node-major mapping for ACC L2 locality.
// dyn smem: 8*1056*4 = 33792 B; static SH 8*384*4 = 12288 B.
__global__ __launch_bounds__(256) void k_upd1(const float* __restrict__ ws_w,
                                              const float* __restrict__ cwg,
                                              const float* __restrict__ mwg,
                                              float* __restrict__ out) {
    extern __shared__ float dsm[];
    __shared__ __align__(16) float SH[8][384];
    int warp = threadIdx.x >> 5, lane = threadIdx.x & 31;
    float* ww = dsm + warp * 1056;
    int wg = blockIdx.x * 8 + warp;
    int node = wg / 3;
    int c = wg - node * 3;
    float* sh = SH[warp];
    int beg = g_off[node], end = g_off[node + 1];
    size_t mbase = (((size_t)3 + c) * NN + node) * 1024;
    const float* wrow = ww + lane * 33;
    const float* ws = ws_w + 288 + lane;   // l=1

    stage_w(cwg + mbase, ww, lane);        // cw staging overlaps the gather below

    if (c == 0) {
        float A0 = 0.f;
        int idx = beg;
        for (; idx + 4 <= end; idx += 4) {
            const float* ap = g_ACC + (size_t)idx * 96 + lane;
            float x0 = __ldcs(ap), x1 = __ldcs(ap + 96);
            float x2 = __ldcs(ap + 192), x3 = __ldcs(ap + 288);
            A0 += (x0 + x1) + (x2 + x3);
        }
        for (; idx < end; idx++)
            A0 += __ldcs(g_ACC + (size_t)idx * 96 + lane);
        float f0 = ws[0] + ws[32] * A0 + ws[64] * A0 * A0;
        sh[lane] = g_H0[node * 32 + lane];
        __syncwarp();
        float o = 0.f;
#pragma unroll
        for (int j = 0; j < 32; j++) o += wrow[j] * sh[j];
        __syncwarp();
        stage_w(mwg + mbase, ww, lane);
        sh[lane] = f0 * A0;
        __syncwarp();
#pragma unroll
        for (int j = 0; j < 32; j++) o += wrow[j] * sh[j];
        out[(node * 32 + lane) * 13 + 0] = o;
    } else if (c == 1) {
        float A0 = 0.f, A1x = 0.f, A1y = 0.f, A1z = 0.f;
        int idx = beg;
        for (; idx + 2 <= end; idx += 2) {
            float4 ua = ((const float4*)g_US)[idx];
            float4 ub = ((const float4*)g_US)[idx + 1];
            const float* ap = g_ACC + (size_t)idx * 96 + lane;
            float a0a = __ldcs(ap),      a1a = __ldcs(ap + 32);
            float a0b = __ldcs(ap + 96), a1b = __ldcs(ap + 128);
            A0 += a0a + a0b;
            A1x += a1a * ua.x + a1b * ub.x;
            A1y += a1a * ua.y + a1b * ub.y;
            A1z += a1a * ua.z + a1b * ub.z;
        }
        if (idx < end) {
            float4 u = ((const float4*)g_US)[idx];
            const float* ap = g_ACC + (size_t)idx * 96 + lane;
            float a0 = __ldcs(ap), a1 = __ldcs(ap + 32);
            A0 += a0;
            A1x += a1 * u.x; A1y += a1 * u.y; A1z += a1 * u.z;
        }
        float f1 = ws[96] + ws[128] * A0 + ws[160] * A0 * A0;
        const float* hp = g_H1 + node * 96;
        sh[lane * 12 + 0] = hp[lane];
        sh[lane * 12 + 1] = hp[32 + lane];
        sh[lane * 12 + 2] = hp[64 + lane];
        __syncwarp();
        float o0 = 0.f, o1 = 0.f, o2 = 0.f;
#pragma unroll
        for (int j = 0; j < 32; j++) {
            float w1 = wrow[j];
            float2 hv = *(const float2*)&sh[j * 12];
            float  hz = sh[j * 12 + 2];
            o0 += w1 * hv.x; o1 += w1 * hv.y; o2 += w1 * hz;
        }
        __syncwarp();
        stage_w(mwg + mbase, ww, lane);
        sh[lane * 12 + 0] = f1 * A1x;
        sh[lane * 12 + 1] = f1 * A1y;
        sh[lane * 12 + 2] = f1 * A1z;
        __syncwarp();
#pragma unroll
        for (int j = 0; j < 32; j++) {
            float w2 = wrow[j];
            float2 mv = *(const float2*)&sh[j * 12];
            float  mz = sh[j * 12 + 2];
            o0 += w2 * mv.x; o1 += w2 * mv.y; o2 += w2 * mz;
        }
        float* op = out + (node * 32 + lane) * 13 + 1;
        op[0] = o0; op[1] = o1; op[2] = o2;
    } else {
        // symmetric second-moment gather: 6 unique accumulators
        float A0 = 0.f;
        float m00 = 0.f, m01 = 0.f, m02 = 0.f, m11 = 0.f, m12 = 0.f, m22 = 0.f;
        int idx = beg;
        for (; idx + 2 <= end; idx += 2) {
            float4 ua = ((const float4*)g_US)[idx];
            float4 ub = ((const float4*)g_US)[idx + 1];
            const float* ap = g_ACC + (size_t)idx * 96 + lane;
            float a0a = __ldcs(ap),      a2a = __ldcs(ap + 64);
            float a0b = __ldcs(ap + 96), a2b = __ldcs(ap + 160);
            A0 += a0a + a0b;
            float c0 = a2a * ua.x, c1 = a2a * ua.y, c2 = a2a * ua.z;
            float d0 = a2b * ub.x, d1 = a2b * ub.y, d2 = a2b * ub.z;
            m00 += c0 * ua.x + d0 * ub.x;
            m01 += c0 * ua.y + d0 * ub.y;
            m02 += c0 * ua.z + d0 * ub.z;
            m11 += c1 * ua.y + d1 * ub.y;
            m12 += c1 * ua.z + d1 * ub.z;
            m22 += c2 * ua.z + d2 * ub.z;
        }
        if (idx < end) {
            float4 u = ((const float4*)g_US)[idx];
            const float* ap = g_ACC + (size_t)idx * 96 + lane;
            float a0 = __ldcs(ap), a2 = __ldcs(ap + 64);
            A0 += a0;
            float b0 = a2 * u.x, b1 = a2 * u.y, b2 = a2 * u.z;
            m00 += b0 * u.x; m01 += b0 * u.y; m02 += b0 * u.z;
            m11 += b1 * u.y; m12 += b1 * u.z; m22 += b2 * u.z;
        }
        float f2 = ws[192] + ws[224] * A0 + ws[256] * A0 * A0;
        const float* hp = g_H2 + node * 288;
#pragma unroll
        for (int d = 0; d < 9; d++) sh[lane * 12 + d] = hp[d * 32 + lane];
        __syncwarp();
        float o[9];
#pragma unroll
        for (int d = 0; d < 9; d++) o[d] = 0.f;
#pragma unroll
        for (int j = 0; j < 32; j++) {
            float w1 = wrow[j];
            float4 ha = *(const float4*)&sh[j * 12];
            float4 hb = *(const float4*)&sh[j * 12 + 4];
            float  hc = sh[j * 12 + 8];
            o[0] += w1 * ha.x; o[1] += w1 * ha.y; o[2] += w1 * ha.z; o[3] += w1 * ha.w;
            o[4] += w1 * hb.x; o[5] += w1 * hb.y; o[6] += w1 * hb.z; o[7] += w1 * hb.w;
            o[8] += w1 * hc;
        }
        __syncwarp();
        stage_w(mwg + mbase, ww, lane);
        sh[lane * 12 + 0] = f2 * m00;
        sh[lane * 12 + 1] = f2 * m01;
        sh[lane * 12 + 2] = f2 * m02;
        sh[lane * 12 + 3] = f2 * m01;
        sh[lane * 12 + 4] = f2 * m11;
        sh[lane * 12 + 5] = f2 * m12;
        sh[lane * 12 + 6] = f2 * m02;
        sh[lane * 12 + 7] = f2 * m12;
        sh[lane * 12 + 8] = f2 * m22;
        __syncwarp();
#pragma unroll
        for (int j = 0; j < 32; j++) {
            float w2 = wrow[j];
            float4 ma = *(const float4*)&sh[j * 12];
            float4 mb = *(const float4*)&sh[j * 12 + 4];
            float  mc = sh[j * 12 + 8];
            o[0] += w2 * ma.x; o[1] += w2 * ma.y; o[2] += w2 * ma.z; o[3] += w2 * ma.w;
            o[4] += w2 * mb.x; o[5] += w2 * mb.y; o[6] += w2 * mb.z; o[7] += w2 * mb.w;
            o[8] += w2 * mc;
        }
        float* op = out + (node * 32 + lane) * 13 + 4;
#pragma unroll
        for (int d = 0; d < 9; d++) op[d] = o[d];
    }
}

extern "C" void kernel_launch(void* const* d_in, const int* in_sizes, int n_in,
                              void* d_out, int out_size) {
    (void)in_sizes; (void)n_in; (void)out_size;
    const float* pos   = (const float*)d_in[0];
    const int*   ei    = (const int*)d_in[1];
    const int*   atoms = (const int*)d_in[2];
    const float* emb   = (const float*)d_in[3];
    const float* W_ab  = (const float*)d_in[4];
    const float* ws_w  = (const float*)d_in[5];
    const float* cw    = (const float*)d_in[6];
    const float* mw    = (const float*)d_in[7];
    float* out = (float*)d_out;

    const int EDGE_SMEM = (12672 + 3072) * 4;          // 62976 B -> 3 blocks/SM
    const int UPD_SMEM  = 8 * 1056 * 4;                // 33792 B
    cudaFuncSetAttribute(k_edge, cudaFuncAttributeMaxDynamicSharedMemorySize, EDGE_SMEM);
    cudaFuncSetAttribute(k_upd0, cudaFuncAttributeMaxDynamicSharedMemorySize, UPD_SMEM);
    cudaFuncSetAttribute(k_upd1, cudaFuncAttributeMaxDynamicSharedMemorySize, UPD_SMEM);

    k_init<<<1250, 256>>>(emb, atoms, W_ab, ei);
    k_scan<<<1, 1024>>>();
    k_fill<<<625, 256>>>(ei, pos);

    // layer 0 (edge phase analytic; gather fused into update)
    k_upd0<<<3 * NN / 8, 256, UPD_SMEM>>>(ws_w, cw, mw);
    // layer 1 (gather fused into update)
    k_edge<<<NE / 128, 256, EDGE_SMEM>>>(W_ab);
    k_upd1<<<3 * NN / 8, 256, UPD_SMEM>>>(ws_w, cw, mw, out);
}

// round 14
// speedup vs baseline: 1.0318x; 1.0318x over previous
#include <cuda_runtime.h>
#include <math.h>

#define NN 10000
#define NE 160000

// ---------------- scratch (static device globals; no allocation) ----------------
__device__ float g_US[NE * 4];           // sorted unit vectors (float4 per CSR slot)
__device__ int   g_srcs[NE];             // sorted src node per CSR slot
__device__ int   g_cnt[NN];              // INVARIANT: zero at kernel_launch entry/exit
__device__ int   g_off[NN + 1];
__device__ int   g_cur[NN];
__device__ float g_H0[NN * 32];          // (N,C)
__device__ float g_H1[NN * 96];          // (N, d-major: d*32 + ch)
__device__ float g_H2[NN * 288];         // (N, d-major: d*32 + ch)
__device__ float g_ACC[NE * 96];         // per-CSR-slot acc (k index)
__device__ float g_accvec[96];           // layer-0 constant acc vector

// ---------------- packed f32x2 helpers ----------------
__device__ __forceinline__ unsigned long long pack2(float x, float y) {
    unsigned long long r; asm("mov.b64 %0, {%1,%2};" : "=l"(r) : "f"(x), "f"(y)); return r;
}
__device__ __forceinline__ void unpack2(unsigned long long v, float& x, float& y) {
    asm("mov.b64 {%0,%1}, %2;" : "=f"(x), "=f"(y) : "l"(v));
}
__device__ __forceinline__ unsigned long long fma2(unsigned long long a, unsigned long long b,
                                                   unsigned long long c) {
    unsigned long long d;
    asm("fma.rn.f32x2 %0, %1, %2, %3;" : "=l"(d) : "l"(a), "l"(b), "l"(c));
    return d;
}

// Stage a 32x32 weight matrix (1024 contiguous floats) into shared, coalesced.
// Evict-first global loads: weights are read exactly once, keep L2 for H/ACC.
// ww layout: row r at ww[r*33 .. r*33+31] (stride 33 => conflict-free STS & LDS).
__device__ __forceinline__ void stage_w(const float* __restrict__ g, float* ww, int lane) {
#pragma unroll
    for (int q = 0; q < 8; q++) {
        float4 v = __ldcs(((const float4*)g) + q * 32 + lane);
        int r = q * 4 + (lane >> 3);
        float* p = ww + r * 33 + (lane & 7) * 4;
        p[0] = v.x; p[1] = v.y; p[2] = v.z; p[3] = v.w;
    }
}

// ---------------- init: embed atoms, dst histogram, layer-0 accvec ----------------
__global__ void k_init(const float* __restrict__ emb, const int* __restrict__ atoms,
                       const float* __restrict__ W_ab, const int* __restrict__ ei) {
    int t = blockIdx.x * 256 + threadIdx.x;
    if (t < NN * 32) g_H0[t] = emb[atoms[t >> 5] * 32 + (t & 31)];
    if (t < NE)      atomicAdd(&g_cnt[ei[NE + t]], 1);
    if (t < 96) {
        int c = t >> 5, j = t & 31;
        const float* wp = W_ab + (c * 3) * 1024 + j * 32;
        float s = 0.f;
#pragma unroll
        for (int k = 0; k < 32; k++) s += wp[k] * emb[k];
        g_accvec[t] = s;
    }
}

// ---------------- single-block exclusive scan; re-zeroes g_cnt ----------------
__global__ void k_scan() {
    __shared__ int sh[1024];
    int t = threadIdx.x;
    const int PER = 10;
    int base = t * PER;
    int loc[PER];
    int s = 0;
#pragma unroll
    for (int i = 0; i < PER; i++) {
        int idx = base + i;
        int v = (idx < NN) ? g_cnt[idx] : 0;
        if (idx < NN) g_cnt[idx] = 0;
        loc[i] = s;
        s += v;
    }
    sh[t] = s;
    __syncthreads();
    for (int off = 1; off < 1024; off <<= 1) {
        int v = (t >= off) ? sh[t - off] : 0;
        __syncthreads();
        sh[t] += v;
        __syncthreads();
    }
    int excl = sh[t] - s;
#pragma unroll
    for (int i = 0; i < PER; i++) {
        int idx = base + i;
        if (idx < NN) { g_off[idx] = excl + loc[i]; g_cur[idx] = excl + loc[i]; }
    }
    if (t == 1023) g_off[NN] = sh[1023];
}

// ---------------- geometry + scatter into CSR order ----------------
__global__ void k_fill(const int* __restrict__ ei, const float* __restrict__ pos) {
    int e = blockIdx.x * 256 + threadIdx.x;
    if (e >= NE) return;
    int s = ei[e], d = ei[NE + e];
    float rx = pos[d * 3 + 0] - pos[s * 3 + 0];
    float ry = pos[d * 3 + 1] - pos[s * 3 + 1];
    float rz = pos[d * 3 + 2] - pos[s * 3 + 2];
    float nrm = sqrtf(rx * rx + ry * ry + rz * rz);
    float inv = 1.0f / (nrm + 1e-9f);
    int p = atomicAdd(&g_cur[d], 1);
    g_srcs[p] = s;
    ((float4*)g_US)[p] = make_float4(rx * inv, ry * inv, rz * inv, 0.f);
}

// ---------------- layer-0 fused gather+update: warp per (node, c) ----------------
// node-major warp mapping: node = wg/3, c = wg%3.
// dyn smem: 8 * 1056 * 4 = 33792 B.
__global__ __launch_bounds__(256) void k_upd0(const float* __restrict__ ws_w,
                                              const float* __restrict__ cwg,
                                              const float* __restrict__ mwg) {
    extern __shared__ float dsm[];
    __shared__ float FS[8][32];
    __shared__ float HS[8][32];
    int warp = threadIdx.x >> 5, lane = threadIdx.x & 31;
    float* ww = dsm + warp * 1056;
    int wg = blockIdx.x * 8 + warp;
    int node = wg / 3;
    int c = wg - node * 3;
    int beg = g_off[node], end = g_off[node + 1];
    float cnt = (float)(end - beg);
    float s0 = g_accvec[lane] * cnt;
    float s0q = s0 * s0;
    const float* ws = ws_w + lane;                // l = 0
    size_t mbase = ((size_t)c * NN + node) * 1024;
    const float* wrow = ww + lane * 33;

    if (c == 0) {
        stage_w(mwg + mbase, ww, lane);
        float f0 = ws[0] + ws[32] * s0 + ws[64] * s0q;
        FS[warp][lane] = f0 * s0;                 // M0
        HS[warp][lane] = g_H0[node * 32 + lane];
        __syncwarp();
        float o = 0.f;
#pragma unroll
        for (int j = 0; j < 32; j++) o += wrow[j] * FS[warp][j];
        __syncwarp();
        stage_w(cwg + mbase, ww, lane);
        __syncwarp();
#pragma unroll
        for (int j = 0; j < 32; j++) o += wrow[j] * HS[warp][j];
        g_H0[node * 32 + lane] = o;
    } else if (c == 1) {
        stage_w(mwg + mbase, ww, lane);
        float su0 = 0, su1 = 0, su2 = 0;
        for (int idx = beg + lane; idx < end; idx += 32) {
            float4 u = ((const float4*)g_US)[idx];
            su0 += u.x; su1 += u.y; su2 += u.z;
        }
#pragma unroll
        for (int off = 16; off; off >>= 1) {
            su0 += __shfl_xor_sync(~0u, su0, off);
            su1 += __shfl_xor_sync(~0u, su1, off);
            su2 += __shfl_xor_sync(~0u, su2, off);
        }
        float f1 = ws[96] + ws[128] * s0 + ws[160] * s0q;
        FS[warp][lane] = f1 * g_accvec[32 + lane];
        __syncwarp();
        float t = 0.f;
#pragma unroll
        for (int j = 0; j < 32; j++) t += wrow[j] * FS[warp][j];
        __syncwarp();
        float* op = g_H1 + node * 96;
        op[lane] = su0 * t; op[32 + lane] = su1 * t; op[64 + lane] = su2 * t;
    } else {
        stage_w(mwg + mbase, ww, lane);
        float s00 = 0, s01 = 0, s02 = 0, s11 = 0, s12 = 0, s22 = 0;
        for (int idx = beg + lane; idx < end; idx += 32) {
            float4 u = ((const float4*)g_US)[idx];
            s00 += u.x * u.x; s01 += u.x * u.y; s02 += u.x * u.z;
            s11 += u.y * u.y; s12 += u.y * u.z; s22 += u.z * u.z;
        }
#pragma unroll
        for (int off = 16; off; off >>= 1) {
            s00 += __shfl_xor_sync(~0u, s00, off);
            s01 += __shfl_xor_sync(~0u, s01, off);
            s02 += __shfl_xor_sync(~0u, s02, off);
            s11 += __shfl_xor_sync(~0u, s11, off);
            s12 += __shfl_xor_sync(~0u, s12, off);
            s22 += __shfl_xor_sync(~0u, s22, off);
        }
        float f2 = ws[192] + ws[224] * s0 + ws[256] * s0q;
        FS[warp][lane] = f2 * g_accvec[64 + lane];
        __syncwarp();
        float t = 0.f;
#pragma unroll
        for (int j = 0; j < 32; j++) t += wrow[j] * FS[warp][j];
        __syncwarp();
        float* op = g_H2 + node * 288;
        op[lane]       = s00 * t; op[32 + lane]  = s01 * t; op[64 + lane]  = s02 * t;
        op[96 + lane]  = s01 * t; op[128 + lane] = s11 * t; op[160 + lane] = s12 * t;
        op[192 + lane] = s02 * t; op[224 + lane] = s12 * t; op[256 + lane] = s22 * t;
    }
}

// ---------------- layer-1 edge kernel: fused S-build + (96x96)@(96xE) GEMM -------
// R12 structure (proven fastest): all W resident, single __syncthreads.
// 256 threads / 128 CSR slots; thread tile 6k x 8e (mg in [0,16), ng in [0,16)).
// Dyn smem: 9216 + 3*128*33 = 21888 floats = 87552 B.
__global__ __launch_bounds__(256) void k_edge(const float* __restrict__ W_ab) {
    extern __shared__ float sm[];
    float* Wt = sm;
    float* Ss = sm + 9216;     // [a*4224 + e_loc*33 + j]
    int tid = threadIdx.x;
    int warp = tid >> 5, lane = tid & 31;
    int mg = tid & 15;
    int ng = tid >> 4;
    int e_base = blockIdx.x * 128;

#pragma unroll 4
    for (int t2 = 0; t2 < 16; t2++) {
        int e_loc = warp * 16 + t2;
        int idx = e_base + e_loc;
        int src = g_srcs[idx];
        float4 u = ((const float4*)g_US)[idx];
        float s0 = g_H0[src * 32 + lane];
        const float* h1 = g_H1 + src * 96;
        float s1 = h1[lane] * u.x + h1[32 + lane] * u.y + h1[64 + lane] * u.z;
        const float* h2 = g_H2 + src * 288;
        float s2 = u.x * (h2[lane] * u.x + h2[32 + lane] * u.y + h2[64 + lane] * u.z)
                 + u.y * (h2[96 + lane] * u.x + h2[128 + lane] * u.y + h2[160 + lane] * u.z)
                 + u.z * (h2[192 + lane] * u.x + h2[224 + lane] * u.y + h2[256 + lane] * u.z);
        Ss[e_loc * 33 + lane] = s0;
        Ss[4224 + e_loc * 33 + lane] = s1;
        Ss[8448 + e_loc * 33 + lane] = s2;
    }
    for (int t = tid; t < 9216; t += 256) {
        int a = t / 3072, rem = t - a * 3072;
        int j = rem / 96, r = rem - j * 96;
        int mgi = r / 6, kki = r - mgi * 6;
        int k = mgi + 16 * kki;
        Wt[t] = __ldcs(&W_ab[((3 + (k >> 5)) * 3 + a) * 1024 + (k & 31) * 32 + j]);
    }
    __syncthreads();

    unsigned long long acc2[3][8];
#pragma unroll
    for (int p = 0; p < 3; p++)
#pragma unroll
        for (int ee = 0; ee < 8; ee++) acc2[p][ee] = 0ull;

#pragma unroll
    for (int a = 0; a < 3; a++) {
        const float* Wa = Wt + a * 3072;
        const float* Sa = Ss + a * 4224;
#pragma unroll 8
        for (int j = 0; j < 32; j++) {
            const unsigned long long* wp =
                (const unsigned long long*)&Wa[j * 96 + mg * 6];
            unsigned long long w0 = wp[0], w1 = wp[1], w2 = wp[2];
            unsigned long long s2v[8];
#pragma unroll
            for (int ee = 0; ee < 8; ee++) {
                float s = Sa[(ng + 16 * ee) * 33 + j];
                s2v[ee] = pack2(s, s);
            }
#pragma unroll
            for (int ee = 0; ee < 8; ee++) {
                acc2[0][ee] = fma2(w0, s2v[ee], acc2[0][ee]);
                acc2[1][ee] = fma2(w1, s2v[ee], acc2[1][ee]);
                acc2[2][ee] = fma2(w2, s2v[ee], acc2[2][ee]);
            }
        }
    }
#pragma unroll
    for (int ee = 0; ee < 8; ee++) {
        int idx = e_base + ng + 16 * ee;
        float* op = g_ACC + (size_t)idx * 96 + mg;
#pragma unroll
        for (int p = 0; p < 3; p++) {
            float lo, hi;
            unpack2(acc2[p][ee], lo, hi);
            op[16 * (2 * p)]     = lo;
            op[16 * (2 * p + 1)] = hi;
        }
    }
}

// ---------------- layer-1 fused gather+update: warp per (node, c) ----------------
// Gather at entry (overlaps cw staging); node-major mapping for ACC L2 locality;
// symmetric 6-accumulator A2 gather; x4-unrolled c=0 gather.
// dyn smem: 8*1056*4 = 33792 B; static SH 8*384*4 = 12288 B.
__global__ __launch_bounds__(256) void k_upd1(const float* __restrict__ ws_w,
                                              const float* __restrict__ cwg,
                                              const float* __restrict__ mwg,
                                              float* __restrict__ out) {
    extern __shared__ float dsm[];
    __shared__ __align__(16) float SH[8][384];
    int warp = threadIdx.x >> 5, lane = threadIdx.x & 31;
    float* ww = dsm + warp * 1056;
    int wg = blockIdx.x * 8 + warp;
    int node = wg / 3;
    int c = wg - node * 3;
    float* sh = SH[warp];
    int beg = g_off[node], end = g_off[node + 1];
    size_t mbase = (((size_t)3 + c) * NN + node) * 1024;
    const float* wrow = ww + lane * 33;
    const float* ws = ws_w + 288 + lane;   // l=1

    stage_w(cwg + mbase, ww, lane);        // cw staging overlaps the gather below

    if (c == 0) {
        float A0 = 0.f;
        int idx = beg;
        for (; idx + 4 <= end; idx += 4) {
            const float* ap = g_ACC + (size_t)idx * 96 + lane;
            float x0 = __ldcs(ap), x1 = __ldcs(ap + 96);
            float x2 = __ldcs(ap + 192), x3 = __ldcs(ap + 288);
            A0 += (x0 + x1) + (x2 + x3);
        }
        for (; idx < end; idx++)
            A0 += __ldcs(g_ACC + (size_t)idx * 96 + lane);
        float f0 = ws[0] + ws[32] * A0 + ws[64] * A0 * A0;
        sh[lane] = g_H0[node * 32 + lane];
        __syncwarp();
        float o = 0.f;
#pragma unroll
        for (int j = 0; j < 32; j++) o += wrow[j] * sh[j];
        __syncwarp();
        stage_w(mwg + mbase, ww, lane);
        sh[lane] = f0 * A0;
        __syncwarp();
#pragma unroll
        for (int j = 0; j < 32; j++) o += wrow[j] * sh[j];
        out[(node * 32 + lane) * 13 + 0] = o;
    } else if (c == 1) {
        float A0 = 0.f, A1x = 0.f, A1y = 0.f, A1z = 0.f;
        int idx = beg;
        for (; idx + 2 <= end; idx += 2) {
            float4 ua = ((const float4*)g_US)[idx];
            float4 ub = ((const float4*)g_US)[idx + 1];
            const float* ap = g_ACC + (size_t)idx * 96 + lane;
            float a0a = __ldcs(ap),      a1a = __ldcs(ap + 32);
            float a0b = __ldcs(ap + 96), a1b = __ldcs(ap + 128);
            A0 += a0a + a0b;
            A1x += a1a * ua.x + a1b * ub.x;
            A1y += a1a * ua.y + a1b * ub.y;
            A1z += a1a * ua.z + a1b * ub.z;
        }
        if (idx < end) {
            float4 u = ((const float4*)g_US)[idx];
            const float* ap = g_ACC + (size_t)idx * 96 + lane;
            float a0 = __ldcs(ap), a1 = __ldcs(ap + 32);
            A0 += a0;
            A1x += a1 * u.x; A1y += a1 * u.y; A1z += a1 * u.z;
        }
        float f1 = ws[96] + ws[128] * A0 + ws[160] * A0 * A0;
        const float* hp = g_H1 + node * 96;
        sh[lane * 12 + 0] = hp[lane];
        sh[lane * 12 + 1] = hp[32 + lane];
        sh[lane * 12 + 2] = hp[64 + lane];
        __syncwarp();
        float o0 = 0.f, o1 = 0.f, o2 = 0.f;
#pragma unroll
        for (int j = 0; j < 32; j++) {
            float w1 = wrow[j];
            float2 hv = *(const float2*)&sh[j * 12];
            float  hz = sh[j * 12 + 2];
            o0 += w1 * hv.x; o1 += w1 * hv.y; o2 += w1 * hz;
        }
        __syncwarp();
        stage_w(mwg + mbase, ww, lane);
        sh[lane * 12 + 0] = f1 * A1x;
        sh[lane * 12 + 1] = f1 * A1y;
        sh[lane * 12 + 2] = f1 * A1z;
        __syncwarp();
#pragma unroll
        for (int j = 0; j < 32; j++) {
            float w2 = wrow[j];
            float2 mv = *(const float2*)&sh[j * 12];
            float  mz = sh[j * 12 + 2];
            o0 += w2 * mv.x; o1 += w2 * mv.y; o2 += w2 * mz;
        }
        float* op = out + (node * 32 + lane) * 13 + 1;
        op[0] = o0; op[1] = o1; op[2] = o2;
    } else {
        // symmetric second-moment gather: 6 unique accumulators
        float A0 = 0.f;
        float m00 = 0.f, m01 = 0.f, m02 = 0.f, m11 = 0.f, m12 = 0.f, m22 = 0.f;
        int idx = beg;
        for (; idx + 2 <= end; idx += 2) {
            float4 ua = ((const float4*)g_US)[idx];
            float4 ub = ((const float4*)g_US)[idx + 1];
            const float* ap = g_ACC + (size_t)idx * 96 + lane;
            float a0a = __ldcs(ap),      a2a = __ldcs(ap + 64);
            float a0b = __ldcs(ap + 96), a2b = __ldcs(ap + 160);
            A0 += a0a + a0b;
            float c0 = a2a * ua.x, c1 = a2a * ua.y, c2 = a2a * ua.z;
            float d0 = a2b * ub.x, d1 = a2b * ub.y, d2 = a2b * ub.z;
            m00 += c0 * ua.x + d0 * ub.x;
            m01 += c0 * ua.y + d0 * ub.y;
            m02 += c0 * ua.z + d0 * ub.z;
            m11 += c1 * ua.y + d1 * ub.y;
            m12 += c1 * ua.z + d1 * ub.z;
            m22 += c2 * ua.z + d2 * ub.z;
        }
        if (idx < end) {
            float4 u = ((const float4*)g_US)[idx];
            const float* ap = g_ACC + (size_t)idx * 96 + lane;
            float a0 = __ldcs(ap), a2 = __ldcs(ap + 64);
            A0 += a0;
            float b0 = a2 * u.x, b1 = a2 * u.y, b2 = a2 * u.z;
            m00 += b0 * u.x; m01 += b0 * u.y; m02 += b0 * u.z;
            m11 += b1 * u.y; m12 += b1 * u.z; m22 += b2 * u.z;
        }
        float f2 = ws[192] + ws[224] * A0 + ws[256] * A0 * A0;
        const float* hp = g_H2 + node * 288;
#pragma unroll
        for (int d = 0; d < 9; d++) sh[lane * 12 + d] = hp[d * 32 + lane];
        __syncwarp();
        float o[9];
#pragma unroll
        for (int d = 0; d < 9; d++) o[d] = 0.f;
#pragma unroll
        for (int j = 0; j < 32; j++) {
            float w1 = wrow[j];
            float4 ha = *(const float4*)&sh[j * 12];
            float4 hb = *(const float4*)&sh[j * 12 + 4];
            float  hc = sh[j * 12 + 8];
            o[0] += w1 * ha.x; o[1] += w1 * ha.y; o[2] += w1 * ha.z; o[3] += w1 * ha.w;
            o[4] += w1 * hb.x; o[5] += w1 * hb.y; o[6] += w1 * hb.z; o[7] += w1 * hb.w;
            o[8] += w1 * hc;
        }
        __syncwarp();
        stage_w(mwg + mbase, ww, lane);
        sh[lane * 12 + 0] = f2 * m00;
        sh[lane * 12 + 1] = f2 * m01;
        sh[lane * 12 + 2] = f2 * m02;
        sh[lane * 12 + 3] = f2 * m01;
        sh[lane * 12 + 4] = f2 * m11;
        sh[lane * 12 + 5] = f2 * m12;
        sh[lane * 12 + 6] = f2 * m02;
        sh[lane * 12 + 7] = f2 * m12;
        sh[lane * 12 + 8] = f2 * m22;
        __syncwarp();
#pragma unroll
        for (int j = 0; j < 32; j++) {
            float w2 = wrow[j];
            float4 ma = *(const float4*)&sh[j * 12];
            float4 mb = *(const float4*)&sh[j * 12 + 4];
            float  mc = sh[j * 12 + 8];
            o[0] += w2 * ma.x; o[1] += w2 * ma.y; o[2] += w2 * ma.z; o[3] += w2 * ma.w;
            o[4] += w2 * mb.x; o[5] += w2 * mb.y; o[6] += w2 * mb.z; o[7] += w2 * mb.w;
            o[8] += w2 * mc;
        }
        float* op = out + (node * 32 + lane) * 13 + 4;
#pragma unroll
        for (int d = 0; d < 9; d++) op[d] = o[d];
    }
}

extern "C" void kernel_launch(void* const* d_in, const int* in_sizes, int n_in,
                              void* d_out, int out_size) {
    (void)in_sizes; (void)n_in; (void)out_size;
    const float* pos   = (const float*)d_in[0];
    const int*   ei    = (const int*)d_in[1];
    const int*   atoms = (const int*)d_in[2];
    const float* emb   = (const float*)d_in[3];
    const float* W_ab  = (const float*)d_in[4];
    const float* ws_w  = (const float*)d_in[5];
    const float* cw    = (const float*)d_in[6];
    const float* mw    = (const float*)d_in[7];
    float* out = (float*)d_out;

    const int EDGE_SMEM = (9216 + 3 * 128 * 33) * 4;   // 87552 B (R12 structure)
    const int UPD_SMEM  = 8 * 1056 * 4;                // 33792 B
    cudaFuncSetAttribute(k_edge, cudaFuncAttributeMaxDynamicSharedMemorySize, EDGE_SMEM);
    cudaFuncSetAttribute(k_upd0, cudaFuncAttributeMaxDynamicSharedMemorySize, UPD_SMEM);
    cudaFuncSetAttribute(k_upd1, cudaFuncAttributeMaxDynamicSharedMemorySize, UPD_SMEM);

    k_init<<<1250, 256>>>(emb, atoms, W_ab, ei);
    k_scan<<<1, 1024>>>();
    k_fill<<<625, 256>>>(ei, pos);

    // layer 0 (edge phase analytic; gather fused into update)
    k_upd0<<<3 * NN / 8, 256, UPD_SMEM>>>(ws_w, cw, mw);
    // layer 1 (gather fused into update)
    k_edge<<<NE / 128, 256, EDGE_SMEM>>>(W_ab);
    k_upd1<<<3 * NN / 8, 256, UPD_SMEM>>>(ws_w, cw, mw, out);
}

// round 15
// speedup vs baseline: 1.0426x; 1.0104x over previous
#include <cuda_runtime.h>
#include <math.h>

#define NN 10000
#define NE 160000

// ---------------- scratch (static device globals; no allocation) ----------------
__device__ float g_US[NE * 4];           // sorted unit vectors (float4 per CSR slot)
__device__ int   g_srcs[NE];             // sorted src node per CSR slot
__device__ int   g_cnt[NN];              // INVARIANT: zero at kernel_launch entry/exit
__device__ int   g_off[NN + 1];
__device__ int   g_cur[NN];
__device__ float g_H0[NN * 32];          // (N,C)
__device__ float g_H1[NN * 96];          // (N, d-major: d*32 + ch)
__device__ float g_H2[NN * 288];         // (N, d-major: d*32 + ch)
__device__ float g_ACC[NE * 96];         // per-CSR-slot acc (k index)
__device__ float g_accvec[96];           // layer-0 constant acc vector

// ---------------- packed f32x2 helpers ----------------
__device__ __forceinline__ unsigned long long pack2(float x, float y) {
    unsigned long long r; asm("mov.b64 %0, {%1,%2};" : "=l"(r) : "f"(x), "f"(y)); return r;
}
__device__ __forceinline__ void unpack2(unsigned long long v, float& x, float& y) {
    asm("mov.b64 {%0,%1}, %2;" : "=f"(x), "=f"(y) : "l"(v));
}
__device__ __forceinline__ unsigned long long fma2(unsigned long long a, unsigned long long b,
                                                   unsigned long long c) {
    unsigned long long d;
    asm("fma.rn.f32x2 %0, %1, %2, %3;" : "=l"(d) : "l"(a), "l"(b), "l"(c));
    return d;
}

// Stage a 32x32 weight matrix (1024 contiguous floats) into shared, coalesced.
// Evict-first global loads: weights are read exactly once, keep L2 for H/ACC.
// ww layout: row r at ww[r*33 .. r*33+31] (stride 33 => conflict-free STS & LDS).
__device__ __forceinline__ void stage_w(const float* __restrict__ g, float* ww, int lane) {
#pragma unroll
    for (int q = 0; q < 8; q++) {
        float4 v = __ldcs(((const float4*)g) + q * 32 + lane);
        int r = q * 4 + (lane >> 3);
        float* p = ww + r * 33 + (lane & 7) * 4;
        p[0] = v.x; p[1] = v.y; p[2] = v.z; p[3] = v.w;
    }
}

// ---------------- init: embed atoms, dst histogram, layer-0 accvec ----------------
__global__ void k_init(const float* __restrict__ emb, const int* __restrict__ atoms,
                       const float* __restrict__ W_ab, const int* __restrict__ ei) {
    int t = blockIdx.x * 256 + threadIdx.x;
    if (t < NN * 32) g_H0[t] = emb[atoms[t >> 5] * 32 + (t & 31)];
    if (t < NE)      atomicAdd(&g_cnt[ei[NE + t]], 1);
    if (t < 96) {
        int c = t >> 5, j = t & 31;
        const float* wp = W_ab + (c * 3) * 1024 + j * 32;
        float s = 0.f;
#pragma unroll
        for (int k = 0; k < 32; k++) s += wp[k] * emb[k];
        g_accvec[t] = s;
    }
}

// ---------------- single-block exclusive scan; re-zeroes g_cnt ----------------
__global__ void k_scan() {
    __shared__ int sh[1024];
    int t = threadIdx.x;
    const int PER = 10;
    int base = t * PER;
    int loc[PER];
    int s = 0;
#pragma unroll
    for (int i = 0; i < PER; i++) {
        int idx = base + i;
        int v = (idx < NN) ? g_cnt[idx] : 0;
        if (idx < NN) g_cnt[idx] = 0;
        loc[i] = s;
        s += v;
    }
    sh[t] = s;
    __syncthreads();
    for (int off = 1; off < 1024; off <<= 1) {
        int v = (t >= off) ? sh[t - off] : 0;
        __syncthreads();
        sh[t] += v;
        __syncthreads();
    }
    int excl = sh[t] - s;
#pragma unroll
    for (int i = 0; i < PER; i++) {
        int idx = base + i;
        if (idx < NN) { g_off[idx] = excl + loc[i]; g_cur[idx] = excl + loc[i]; }
    }
    if (t == 1023) g_off[NN] = sh[1023];
}

// ---------------- geometry + scatter into CSR order ----------------
__global__ void k_fill(const int* __restrict__ ei, const float* __restrict__ pos) {
    int e = blockIdx.x * 256 + threadIdx.x;
    if (e >= NE) return;
    int s = ei[e], d = ei[NE + e];
    float rx = pos[d * 3 + 0] - pos[s * 3 + 0];
    float ry = pos[d * 3 + 1] - pos[s * 3 + 1];
    float rz = pos[d * 3 + 2] - pos[s * 3 + 2];
    float nrm = sqrtf(rx * rx + ry * ry + rz * rz);
    float inv = 1.0f / (nrm + 1e-9f);
    int p = atomicAdd(&g_cur[d], 1);
    g_srcs[p] = s;
    ((float4*)g_US)[p] = make_float4(rx * inv, ry * inv, rz * inv, 0.f);
}

// ---------------- layer-0 fused gather+update: warp per (node, c) ----------------
// 128-thread blocks (4 warps): 24 KB/block -> 9 blocks/SM = 36 warps.
// node-major warp mapping: node = wg/3, c = wg%3. dyn smem: 4*1056*4 = 16896 B.
__global__ __launch_bounds__(128) void k_upd0(const float* __restrict__ ws_w,
                                              const float* __restrict__ cwg,
                                              const float* __restrict__ mwg) {
    extern __shared__ float dsm[];
    __shared__ float FS[4][32];
    __shared__ float HS[4][32];
    int warp = threadIdx.x >> 5, lane = threadIdx.x & 31;
    float* ww = dsm + warp * 1056;
    int wg = blockIdx.x * 4 + warp;
    int node = wg / 3;
    int c = wg - node * 3;
    int beg = g_off[node], end = g_off[node + 1];
    float cnt = (float)(end - beg);
    float s0 = g_accvec[lane] * cnt;
    float s0q = s0 * s0;
    const float* ws = ws_w + lane;                // l = 0
    size_t mbase = ((size_t)c * NN + node) * 1024;
    const float* wrow = ww + lane * 33;

    if (c == 0) {
        stage_w(mwg + mbase, ww, lane);
        float f0 = ws[0] + ws[32] * s0 + ws[64] * s0q;
        FS[warp][lane] = f0 * s0;                 // M0
        HS[warp][lane] = g_H0[node * 32 + lane];
        __syncwarp();
        float o = 0.f;
#pragma unroll
        for (int j = 0; j < 32; j++) o += wrow[j] * FS[warp][j];
        __syncwarp();
        stage_w(cwg + mbase, ww, lane);
        __syncwarp();
#pragma unroll
        for (int j = 0; j < 32; j++) o += wrow[j] * HS[warp][j];
        g_H0[node * 32 + lane] = o;
    } else if (c == 1) {
        stage_w(mwg + mbase, ww, lane);
        float su0 = 0, su1 = 0, su2 = 0;
        for (int idx = beg + lane; idx < end; idx += 32) {
            float4 u = ((const float4*)g_US)[idx];
            su0 += u.x; su1 += u.y; su2 += u.z;
        }
#pragma unroll
        for (int off = 16; off; off >>= 1) {
            su0 += __shfl_xor_sync(~0u, su0, off);
            su1 += __shfl_xor_sync(~0u, su1, off);
            su2 += __shfl_xor_sync(~0u, su2, off);
        }
        float f1 = ws[96] + ws[128] * s0 + ws[160] * s0q;
        FS[warp][lane] = f1 * g_accvec[32 + lane];
        __syncwarp();
        float t = 0.f;
#pragma unroll
        for (int j = 0; j < 32; j++) t += wrow[j] * FS[warp][j];
        __syncwarp();
        float* op = g_H1 + node * 96;
        op[lane] = su0 * t; op[32 + lane] = su1 * t; op[64 + lane] = su2 * t;
    } else {
        stage_w(mwg + mbase, ww, lane);
        float s00 = 0, s01 = 0, s02 = 0, s11 = 0, s12 = 0, s22 = 0;
        for (int idx = beg + lane; idx < end; idx += 32) {
            float4 u = ((const float4*)g_US)[idx];
            s00 += u.x * u.x; s01 += u.x * u.y; s02 += u.x * u.z;
            s11 += u.y * u.y; s12 += u.y * u.z; s22 += u.z * u.z;
        }
#pragma unroll
        for (int off = 16; off; off >>= 1) {
            s00 += __shfl_xor_sync(~0u, s00, off);
            s01 += __shfl_xor_sync(~0u, s01, off);
            s02 += __shfl_xor_sync(~0u, s02, off);
            s11 += __shfl_xor_sync(~0u, s11, off);
            s12 += __shfl_xor_sync(~0u, s12, off);
            s22 += __shfl_xor_sync(~0u, s22, off);
        }
        float f2 = ws[192] + ws[224] * s0 + ws[256] * s0q;
        FS[warp][lane] = f2 * g_accvec[64 + lane];
        __syncwarp();
        float t = 0.f;
#pragma unroll
        for (int j = 0; j < 32; j++) t += wrow[j] * FS[warp][j];
        __syncwarp();
        float* op = g_H2 + node * 288;
        op[lane]       = s00 * t; op[32 + lane]  = s01 * t; op[64 + lane]  = s02 * t;
        op[96 + lane]  = s01 * t; op[128 + lane] = s11 * t; op[160 + lane] = s12 * t;
        op[192 + lane] = s02 * t; op[224 + lane] = s12 * t; op[256 + lane] = s22 * t;
    }
}

// ---------------- layer-1 edge kernel: fused S-build + (96x96)@(96xE) GEMM -------
// R12 structure (proven fastest): all W resident, single __syncthreads.
// 256 threads / 128 CSR slots; thread tile 6k x 8e (mg in [0,16), ng in [0,16)).
// Dyn smem: 9216 + 3*128*33 = 21888 floats = 87552 B.
__global__ __launch_bounds__(256) void k_edge(const float* __restrict__ W_ab) {
    extern __shared__ float sm[];
    float* Wt = sm;
    float* Ss = sm + 9216;     // [a*4224 + e_loc*33 + j]
    int tid = threadIdx.x;
    int warp = tid >> 5, lane = tid & 31;
    int mg = tid & 15;
    int ng = tid >> 4;
    int e_base = blockIdx.x * 128;

#pragma unroll 4
    for (int t2 = 0; t2 < 16; t2++) {
        int e_loc = warp * 16 + t2;
        int idx = e_base + e_loc;
        int src = g_srcs[idx];
        float4 u = ((const float4*)g_US)[idx];
        float s0 = g_H0[src * 32 + lane];
        const float* h1 = g_H1 + src * 96;
        float s1 = h1[lane] * u.x + h1[32 + lane] * u.y + h1[64 + lane] * u.z;
        const float* h2 = g_H2 + src * 288;
        float s2 = u.x * (h2[lane] * u.x + h2[32 + lane] * u.y + h2[64 + lane] * u.z)
                 + u.y * (h2[96 + lane] * u.x + h2[128 + lane] * u.y + h2[160 + lane] * u.z)
                 + u.z * (h2[192 + lane] * u.x + h2[224 + lane] * u.y + h2[256 + lane] * u.z);
        Ss[e_loc * 33 + lane] = s0;
        Ss[4224 + e_loc * 33 + lane] = s1;
        Ss[8448 + e_loc * 33 + lane] = s2;
    }
    for (int t = tid; t < 9216; t += 256) {
        int a = t / 3072, rem = t - a * 3072;
        int j = rem / 96, r = rem - j * 96;
        int mgi = r / 6, kki = r - mgi * 6;
        int k = mgi + 16 * kki;
        Wt[t] = __ldcs(&W_ab[((3 + (k >> 5)) * 3 + a) * 1024 + (k & 31) * 32 + j]);
    }
    __syncthreads();

    unsigned long long acc2[3][8];
#pragma unroll
    for (int p = 0; p < 3; p++)
#pragma unroll
        for (int ee = 0; ee < 8; ee++) acc2[p][ee] = 0ull;

#pragma unroll
    for (int a = 0; a < 3; a++) {
        const float* Wa = Wt + a * 3072;
        const float* Sa = Ss + a * 4224;
#pragma unroll 8
        for (int j = 0; j < 32; j++) {
            const unsigned long long* wp =
                (const unsigned long long*)&Wa[j * 96 + mg * 6];
            unsigned long long w0 = wp[0], w1 = wp[1], w2 = wp[2];
            unsigned long long s2v[8];
#pragma unroll
            for (int ee = 0; ee < 8; ee++) {
                float s = Sa[(ng + 16 * ee) * 33 + j];
                s2v[ee] = pack2(s, s);
            }
#pragma unroll
            for (int ee = 0; ee < 8; ee++) {
                acc2[0][ee] = fma2(w0, s2v[ee], acc2[0][ee]);
                acc2[1][ee] = fma2(w1, s2v[ee], acc2[1][ee]);
                acc2[2][ee] = fma2(w2, s2v[ee], acc2[2][ee]);
            }
        }
    }
#pragma unroll
    for (int ee = 0; ee < 8; ee++) {
        int idx = e_base + ng + 16 * ee;
        float* op = g_ACC + (size_t)idx * 96 + mg;
#pragma unroll
        for (int p = 0; p < 3; p++) {
            float lo, hi;
            unpack2(acc2[p][ee], lo, hi);
            op[16 * (2 * p)]     = lo;
            op[16 * (2 * p + 1)] = hi;
        }
    }
}

// ---------------- layer-1 fused gather+update: warp per (node, c) ----------------
// R12 body; 128-thread blocks (4 warps): 24 KB/block -> 9 blocks/SM = 36 warps.
// Gather at entry (overlaps cw staging); node-major mapping for ACC L2 locality.
// dyn smem: 4*1056*4 = 16896 B; static SH 4*384*4 = 6144 B.
__global__ __launch_bounds__(128) void k_upd1(const float* __restrict__ ws_w,
                                              const float* __restrict__ cwg,
                                              const float* __restrict__ mwg,
                                              float* __restrict__ out) {
    extern __shared__ float dsm[];
    __shared__ __align__(16) float SH[4][384];
    int warp = threadIdx.x >> 5, lane = threadIdx.x & 31;
    float* ww = dsm + warp * 1056;
    int wg = blockIdx.x * 4 + warp;
    int node = wg / 3;
    int c = wg - node * 3;
    float* sh = SH[warp];
    int beg = g_off[node], end = g_off[node + 1];
    size_t mbase = (((size_t)3 + c) * NN + node) * 1024;
    const float* wrow = ww + lane * 33;
    const float* ws = ws_w + 288 + lane;   // l=1

    stage_w(cwg + mbase, ww, lane);        // cw staging overlaps the gather below

    if (c == 0) {
        float A0 = 0.f;
#pragma unroll 4
        for (int idx = beg; idx < end; idx++)
            A0 += __ldcs(g_ACC + (size_t)idx * 96 + lane);
        float f0 = ws[0] + ws[32] * A0 + ws[64] * A0 * A0;
        sh[lane] = g_H0[node * 32 + lane];
        __syncwarp();
        float o = 0.f;
#pragma unroll
        for (int j = 0; j < 32; j++) o += wrow[j] * sh[j];
        __syncwarp();
        stage_w(mwg + mbase, ww, lane);
        sh[lane] = f0 * A0;
        __syncwarp();
#pragma unroll
        for (int j = 0; j < 32; j++) o += wrow[j] * sh[j];
        out[(node * 32 + lane) * 13 + 0] = o;
    } else if (c == 1) {
        float A0 = 0.f, A1x = 0.f, A1y = 0.f, A1z = 0.f;
        int idx = beg;
        for (; idx + 2 <= end; idx += 2) {
            float4 ua = ((const float4*)g_US)[idx];
            float4 ub = ((const float4*)g_US)[idx + 1];
            const float* ap = g_ACC + (size_t)idx * 96 + lane;
            float a0a = __ldcs(ap),      a1a = __ldcs(ap + 32);
            float a0b = __ldcs(ap + 96), a1b = __ldcs(ap + 128);
            A0 += a0a + a0b;
            A1x += a1a * ua.x + a1b * ub.x;
            A1y += a1a * ua.y + a1b * ub.y;
            A1z += a1a * ua.z + a1b * ub.z;
        }
        if (idx < end) {
            float4 u = ((const float4*)g_US)[idx];
            const float* ap = g_ACC + (size_t)idx * 96 + lane;
            float a0 = __ldcs(ap), a1 = __ldcs(ap + 32);
            A0 += a0;
            A1x += a1 * u.x; A1y += a1 * u.y; A1z += a1 * u.z;
        }
        float f1 = ws[96] + ws[128] * A0 + ws[160] * A0 * A0;
        const float* hp = g_H1 + node * 96;
        sh[lane * 12 + 0] = hp[lane];
        sh[lane * 12 + 1] = hp[32 + lane];
        sh[lane * 12 + 2] = hp[64 + lane];
        __syncwarp();
        float o0 = 0.f, o1 = 0.f, o2 = 0.f;
#pragma unroll
        for (int j = 0; j < 32; j++) {
            float w1 = wrow[j];
            float2 hv = *(const float2*)&sh[j * 12];
            float  hz = sh[j * 12 + 2];
            o0 += w1 * hv.x; o1 += w1 * hv.y; o2 += w1 * hz;
        }
        __syncwarp();
        stage_w(mwg + mbase, ww, lane);
        sh[lane * 12 + 0] = f1 * A1x;
        sh[lane * 12 + 1] = f1 * A1y;
        sh[lane * 12 + 2] = f1 * A1z;
        __syncwarp();
#pragma unroll
        for (int j = 0; j < 32; j++) {
            float w2 = wrow[j];
            float2 mv = *(const float2*)&sh[j * 12];
            float  mz = sh[j * 12 + 2];
            o0 += w2 * mv.x; o1 += w2 * mv.y; o2 += w2 * mz;
        }
        float* op = out + (node * 32 + lane) * 13 + 1;
        op[0] = o0; op[1] = o1; op[2] = o2;
    } else {
        float A0 = 0.f;
        float A2[9] = {0.f, 0.f, 0.f, 0.f, 0.f, 0.f, 0.f, 0.f, 0.f};
        int idx = beg;
        for (; idx + 2 <= end; idx += 2) {
            float4 ua = ((const float4*)g_US)[idx];
            float4 ub = ((const float4*)g_US)[idx + 1];
            const float* ap = g_ACC + (size_t)idx * 96 + lane;
            float a0a = __ldcs(ap),      a2a = __ldcs(ap + 64);
            float a0b = __ldcs(ap + 96), a2b = __ldcs(ap + 160);
            A0 += a0a + a0b;
            float c0 = a2a * ua.x, c1 = a2a * ua.y, c2 = a2a * ua.z;
            float d0 = a2b * ub.x, d1 = a2b * ub.y, d2 = a2b * ub.z;
            A2[0] += c0 * ua.x + d0 * ub.x; A2[1] += c0 * ua.y + d0 * ub.y; A2[2] += c0 * ua.z + d0 * ub.z;
            A2[3] += c1 * ua.x + d1 * ub.x; A2[4] += c1 * ua.y + d1 * ub.y; A2[5] += c1 * ua.z + d1 * ub.z;
            A2[6] += c2 * ua.x + d2 * ub.x; A2[7] += c2 * ua.y + d2 * ub.y; A2[8] += c2 * ua.z + d2 * ub.z;
        }
        if (idx < end) {
            float4 u = ((const float4*)g_US)[idx];
            const float* ap = g_ACC + (size_t)idx * 96 + lane;
            float a0 = __ldcs(ap), a2 = __ldcs(ap + 64);
            A0 += a0;
            float b0 = a2 * u.x, b1 = a2 * u.y, b2 = a2 * u.z;
            A2[0] += b0 * u.x; A2[1] += b0 * u.y; A2[2] += b0 * u.z;
            A2[3] += b1 * u.x; A2[4] += b1 * u.y; A2[5] += b1 * u.z;
            A2[6] += b2 * u.x; A2[7] += b2 * u.y; A2[8] += b2 * u.z;
        }
        float f2 = ws[192] + ws[224] * A0 + ws[256] * A0 * A0;
        const float* hp = g_H2 + node * 288;
#pragma unroll
        for (int d = 0; d < 9; d++) sh[lane * 12 + d] = hp[d * 32 + lane];
        __syncwarp();
        float o[9];
#pragma unroll
        for (int d = 0; d < 9; d++) o[d] = 0.f;
#pragma unroll
        for (int j = 0; j < 32; j++) {
            float w1 = wrow[j];
            float4 ha = *(const float4*)&sh[j * 12];
            float4 hb = *(const float4*)&sh[j * 12 + 4];
            float  hc = sh[j * 12 + 8];
            o[0] += w1 * ha.x; o[1] += w1 * ha.y; o[2] += w1 * ha.z; o[3] += w1 * ha.w;
            o[4] += w1 * hb.x; o[5] += w1 * hb.y; o[6] += w1 * hb.z; o[7] += w1 * hb.w;
            o[8] += w1 * hc;
        }
        __syncwarp();
        stage_w(mwg + mbase, ww, lane);
#pragma unroll
        for (int d = 0; d < 9; d++) sh[lane * 12 + d] = f2 * A2[d];
        __syncwarp();
#pragma unroll
        for (int j = 0; j < 32; j++) {
            float w2 = wrow[j];
            float4 ma = *(const float4*)&sh[j * 12];
            float4 mb = *(const float4*)&sh[j * 12 + 4];
            float  mc = sh[j * 12 + 8];
            o[0] += w2 * ma.x; o[1] += w2 * ma.y; o[2] += w2 * ma.z; o[3] += w2 * ma.w;
            o[4] += w2 * mb.x; o[5] += w2 * mb.y; o[6] += w2 * mb.z; o[7] += w2 * mb.w;
            o[8] += w2 * mc;
        }
        float* op = out + (node * 32 + lane) * 13 + 4;
#pragma unroll
        for (int d = 0; d < 9; d++) op[d] = o[d];
    }
}

extern "C" void kernel_launch(void* const* d_in, const int* in_sizes, int n_in,
                              void* d_out, int out_size) {
    (void)in_sizes; (void)n_in; (void)out_size;
    const float* pos   = (const float*)d_in[0];
    const int*   ei    = (const int*)d_in[1];
    const int*   atoms = (const int*)d_in[2];
    const float* emb   = (const float*)d_in[3];
    const float* W_ab  = (const float*)d_in[4];
    const float* ws_w  = (const float*)d_in[5];
    const float* cw    = (const float*)d_in[6];
    const float* mw    = (const float*)d_in[7];
    float* out = (float*)d_out;

    const int EDGE_SMEM = (9216 + 3 * 128 * 33) * 4;   // 87552 B (R12 structure)
    const int UPD_SMEM  = 4 * 1056 * 4;                // 16896 B (4-warp blocks)
    cudaFuncSetAttribute(k_edge, cudaFuncAttributeMaxDynamicSharedMemorySize, EDGE_SMEM);
    cudaFuncSetAttribute(k_upd0, cudaFuncAttributeMaxDynamicSharedMemorySize, UPD_SMEM);
    cudaFuncSetAttribute(k_upd1, cudaFuncAttributeMaxDynamicSharedMemorySize, UPD_SMEM);

    k_init<<<1250, 256>>>(emb, atoms, W_ab, ei);
    k_scan<<<1, 1024>>>();
    k_fill<<<625, 256>>>(ei, pos);

    // layer 0 (edge phase analytic; gather fused into update)
    k_upd0<<<3 * NN / 4, 128, UPD_SMEM>>>(ws_w, cw, mw);
    // layer 1 (gather fused into update)
    k_edge<<<NE / 128, 256, EDGE_SMEM>>>(W_ab);
    k_upd1<<<3 * NN / 4, 128, UPD_SMEM>>>(ws_w, cw, mw, out);
}

// round 16
// speedup vs baseline: 1.0772x; 1.0332x over previous
#include <cuda_runtime.h>
#include <math.h>

#define NN 10000
#define NE 160000

// ---------------- scratch (static device globals; no allocation) ----------------
__device__ float g_US[NE * 4];           // sorted unit vectors (float4 per CSR slot)
__device__ int   g_srcs[NE];             // sorted src node per CSR slot
__device__ int   g_cnt[NN];              // INVARIANT: zero at kernel_launch entry/exit
__device__ int   g_off[NN + 1];
__device__ int   g_cur[NN];
__device__ float g_H0[NN * 32];          // (N,C)
__device__ float g_H1[NN * 96];          // (N, d-major: d*32 + ch)
__device__ float g_H2[NN * 288];         // (N, d-major: d*32 + ch)
__device__ float g_ACC[NE * 96];         // per-CSR-slot acc (k index)
__device__ float g_accvec[96];           // layer-0 constant acc vector

// ---------------- packed f32x2 helpers ----------------
__device__ __forceinline__ unsigned long long pack2(float x, float y) {
    unsigned long long r; asm("mov.b64 %0, {%1,%2};" : "=l"(r) : "f"(x), "f"(y)); return r;
}
__device__ __forceinline__ void unpack2(unsigned long long v, float& x, float& y) {
    asm("mov.b64 {%0,%1}, %2;" : "=f"(x), "=f"(y) : "l"(v));
}
__device__ __forceinline__ unsigned long long fma2(unsigned long long a, unsigned long long b,
                                                   unsigned long long c) {
    unsigned long long d;
    asm("fma.rn.f32x2 %0, %1, %2, %3;" : "=l"(d) : "l"(a), "l"(b), "l"(c));
    return d;
}

// Stage a 32x32 weight matrix (1024 contiguous floats) into shared, coalesced.
// Evict-first global loads: weights are read exactly once, keep L2 for H/ACC.
// ww layout: row r at ww[r*33 .. r*33+31] (stride 33 => conflict-free STS & LDS).
__device__ __forceinline__ void stage_w(const float* __restrict__ g, float* ww, int lane) {
#pragma unroll
    for (int q = 0; q < 8; q++) {
        float4 v = __ldcs(((const float4*)g) + q * 32 + lane);
        int r = q * 4 + (lane >> 3);
        float* p = ww + r * 33 + (lane & 7) * 4;
        p[0] = v.x; p[1] = v.y; p[2] = v.z; p[3] = v.w;
    }
}

// ---------------- init: embed atoms, dst histogram, layer-0 accvec ----------------
__global__ void k_init(const float* __restrict__ emb, const int* __restrict__ atoms,
                       const float* __restrict__ W_ab, const int* __restrict__ ei) {
    int t = blockIdx.x * 256 + threadIdx.x;
    if (t < NN * 32) g_H0[t] = emb[atoms[t >> 5] * 32 + (t & 31)];
    if (t < NE)      atomicAdd(&g_cnt[ei[NE + t]], 1);
    if (t < 96) {
        int c = t >> 5, j = t & 31;
        const float* wp = W_ab + (c * 3) * 1024 + j * 32;
        float s = 0.f;
#pragma unroll
        for (int k = 0; k < 32; k++) s += wp[k] * emb[k];
        g_accvec[t] = s;
    }
}

// ---------------- single-block exclusive scan; re-zeroes g_cnt ----------------
__global__ void k_scan() {
    __shared__ int sh[1024];
    int t = threadIdx.x;
    const int PER = 10;
    int base = t * PER;
    int loc[PER];
    int s = 0;
#pragma unroll
    for (int i = 0; i < PER; i++) {
        int idx = base + i;
        int v = (idx < NN) ? g_cnt[idx] : 0;
        if (idx < NN) g_cnt[idx] = 0;
        loc[i] = s;
        s += v;
    }
    sh[t] = s;
    __syncthreads();
    for (int off = 1; off < 1024; off <<= 1) {
        int v = (t >= off) ? sh[t - off] : 0;
        __syncthreads();
        sh[t] += v;
        __syncthreads();
    }
    int excl = sh[t] - s;
#pragma unroll
    for (int i = 0; i < PER; i++) {
        int idx = base + i;
        if (idx < NN) { g_off[idx] = excl + loc[i]; g_cur[idx] = excl + loc[i]; }
    }
    if (t == 1023) g_off[NN] = sh[1023];
}

// ---------------- geometry + scatter into CSR order ----------------
__global__ void k_fill(const int* __restrict__ ei, const float* __restrict__ pos) {
    int e = blockIdx.x * 256 + threadIdx.x;
    if (e >= NE) return;
    int s = ei[e], d = ei[NE + e];
    float rx = pos[d * 3 + 0] - pos[s * 3 + 0];
    float ry = pos[d * 3 + 1] - pos[s * 3 + 1];
    float rz = pos[d * 3 + 2] - pos[s * 3 + 2];
    float nrm = sqrtf(rx * rx + ry * ry + rz * rz);
    float inv = 1.0f / (nrm + 1e-9f);
    int p = atomicAdd(&g_cur[d], 1);
    g_srcs[p] = s;
    ((float4*)g_US)[p] = make_float4(rx * inv, ry * inv, rz * inv, 0.f);
}

// ---------------- layer-0 fused gather+update: warp per (node, c) ----------------
// 128-thread blocks (4 warps). node-major warp mapping: node = wg/3, c = wg%3.
// dyn smem: 4*1056*4 = 16896 B.
__global__ __launch_bounds__(128) void k_upd0(const float* __restrict__ ws_w,
                                              const float* __restrict__ cwg,
                                              const float* __restrict__ mwg) {
    extern __shared__ float dsm[];
    __shared__ float FS[4][32];
    __shared__ float HS[4][32];
    int warp = threadIdx.x >> 5, lane = threadIdx.x & 31;
    float* ww = dsm + warp * 1056;
    int wg = blockIdx.x * 4 + warp;
    int node = wg / 3;
    int c = wg - node * 3;
    int beg = g_off[node], end = g_off[node + 1];
    float cnt = (float)(end - beg);
    float s0 = g_accvec[lane] * cnt;
    float s0q = s0 * s0;
    const float* ws = ws_w + lane;                // l = 0
    size_t mbase = ((size_t)c * NN + node) * 1024;
    const float* wrow = ww + lane * 33;

    if (c == 0) {
        stage_w(mwg + mbase, ww, lane);
        float f0 = ws[0] + ws[32] * s0 + ws[64] * s0q;
        FS[warp][lane] = f0 * s0;                 // M0
        HS[warp][lane] = g_H0[node * 32 + lane];
        __syncwarp();
        float o = 0.f;
#pragma unroll
        for (int j = 0; j < 32; j++) o += wrow[j] * FS[warp][j];
        __syncwarp();
        stage_w(cwg + mbase, ww, lane);
        __syncwarp();
#pragma unroll
        for (int j = 0; j < 32; j++) o += wrow[j] * HS[warp][j];
        g_H0[node * 32 + lane] = o;
    } else if (c == 1) {
        stage_w(mwg + mbase, ww, lane);
        float su0 = 0, su1 = 0, su2 = 0;
        for (int idx = beg + lane; idx < end; idx += 32) {
            float4 u = ((const float4*)g_US)[idx];
            su0 += u.x; su1 += u.y; su2 += u.z;
        }
#pragma unroll
        for (int off = 16; off; off >>= 1) {
            su0 += __shfl_xor_sync(~0u, su0, off);
            su1 += __shfl_xor_sync(~0u, su1, off);
            su2 += __shfl_xor_sync(~0u, su2, off);
        }
        float f1 = ws[96] + ws[128] * s0 + ws[160] * s0q;
        FS[warp][lane] = f1 * g_accvec[32 + lane];
        __syncwarp();
        float t = 0.f;
#pragma unroll
        for (int j = 0; j < 32; j++) t += wrow[j] * FS[warp][j];
        __syncwarp();
        float* op = g_H1 + node * 96;
        op[lane] = su0 * t; op[32 + lane] = su1 * t; op[64 + lane] = su2 * t;
    } else {
        stage_w(mwg + mbase, ww, lane);
        float s00 = 0, s01 = 0, s02 = 0, s11 = 0, s12 = 0, s22 = 0;
        for (int idx = beg + lane; idx < end; idx += 32) {
            float4 u = ((const float4*)g_US)[idx];
            s00 += u.x * u.x; s01 += u.x * u.y; s02 += u.x * u.z;
            s11 += u.y * u.y; s12 += u.y * u.z; s22 += u.z * u.z;
        }
#pragma unroll
        for (int off = 16; off; off >>= 1) {
            s00 += __shfl_xor_sync(~0u, s00, off);
            s01 += __shfl_xor_sync(~0u, s01, off);
            s02 += __shfl_xor_sync(~0u, s02, off);
            s11 += __shfl_xor_sync(~0u, s11, off);
            s12 += __shfl_xor_sync(~0u, s12, off);
            s22 += __shfl_xor_sync(~0u, s22, off);
        }
        float f2 = ws[192] + ws[224] * s0 + ws[256] * s0q;
        FS[warp][lane] = f2 * g_accvec[64 + lane];
        __syncwarp();
        float t = 0.f;
#pragma unroll
        for (int j = 0; j < 32; j++) t += wrow[j] * FS[warp][j];
        __syncwarp();
        float* op = g_H2 + node * 288;
        op[lane]       = s00 * t; op[32 + lane]  = s01 * t; op[64 + lane]  = s02 * t;
        op[96 + lane]  = s01 * t; op[128 + lane] = s11 * t; op[160 + lane] = s12 * t;
        op[192 + lane] = s02 * t; op[224 + lane] = s12 * t; op[256 + lane] = s22 * t;
    }
}

// ---------------- layer-1 edge kernel: fused S-build + (96x96)@(96xE) GEMM -------
// S staged TRANSPOSED: Ss[a*4224 + j*132 + e_loc]; thread owns 8 CONSECUTIVE
// edges (e = ng*8..ng*8+7) so per-j S loads are 2 x LDS.128 (1 wavefront each)
// instead of 8 scalar LDS. Per-j crossbar wavefronts drop 14 -> 8 => FMA-bound.
// Phase-1 stores are 4-way bank-conflicted (stride 132 == 4 mod 32) - net win.
// Dyn smem: 9216 (W) + 3*4224 (S) = 21888 floats = 87552 B (unchanged).
__global__ __launch_bounds__(256) void k_edge(const float* __restrict__ W_ab) {
    extern __shared__ float sm[];
    float* Wt = sm;
    float* Ss = sm + 9216;     // [a*4224 + j*132 + e_loc]
    int tid = threadIdx.x;
    int warp = tid >> 5, lane = tid & 31;
    int mg = tid & 15;
    int ng = tid >> 4;
    int e_base = blockIdx.x * 128;

#pragma unroll 4
    for (int t2 = 0; t2 < 16; t2++) {
        int e_loc = warp * 16 + t2;
        int idx = e_base + e_loc;
        int src = g_srcs[idx];
        float4 u = ((const float4*)g_US)[idx];
        float s0 = g_H0[src * 32 + lane];
        const float* h1 = g_H1 + src * 96;
        float s1 = h1[lane] * u.x + h1[32 + lane] * u.y + h1[64 + lane] * u.z;
        const float* h2 = g_H2 + src * 288;
        float s2 = u.x * (h2[lane] * u.x + h2[32 + lane] * u.y + h2[64 + lane] * u.z)
                 + u.y * (h2[96 + lane] * u.x + h2[128 + lane] * u.y + h2[160 + lane] * u.z)
                 + u.z * (h2[192 + lane] * u.x + h2[224 + lane] * u.y + h2[256 + lane] * u.z);
        Ss[lane * 132 + e_loc] = s0;
        Ss[4224 + lane * 132 + e_loc] = s1;
        Ss[8448 + lane * 132 + e_loc] = s2;
    }
    for (int t = tid; t < 9216; t += 256) {
        int a = t / 3072, rem = t - a * 3072;
        int j = rem / 96, r = rem - j * 96;
        int mgi = r / 6, kki = r - mgi * 6;
        int k = mgi + 16 * kki;
        Wt[t] = __ldcs(&W_ab[((3 + (k >> 5)) * 3 + a) * 1024 + (k & 31) * 32 + j]);
    }
    __syncthreads();

    unsigned long long acc2[3][8];
#pragma unroll
    for (int p = 0; p < 3; p++)
#pragma unroll
        for (int ee = 0; ee < 8; ee++) acc2[p][ee] = 0ull;

#pragma unroll
    for (int a = 0; a < 3; a++) {
        const float* Wa = Wt + a * 3072;
        const float* Sa = Ss + a * 4224;
#pragma unroll 8
        for (int j = 0; j < 32; j++) {
            const unsigned long long* wp =
                (const unsigned long long*)&Wa[j * 96 + mg * 6];
            unsigned long long w0 = wp[0], w1 = wp[1], w2 = wp[2];
            float4 sA = *(const float4*)&Sa[j * 132 + ng * 8];
            float4 sB = *(const float4*)&Sa[j * 132 + ng * 8 + 4];
            unsigned long long s2v[8];
            s2v[0] = pack2(sA.x, sA.x); s2v[1] = pack2(sA.y, sA.y);
            s2v[2] = pack2(sA.z, sA.z); s2v[3] = pack2(sA.w, sA.w);
            s2v[4] = pack2(sB.x, sB.x); s2v[5] = pack2(sB.y, sB.y);
            s2v[6] = pack2(sB.z, sB.z); s2v[7] = pack2(sB.w, sB.w);
#pragma unroll
            for (int ee = 0; ee < 8; ee++) {
                acc2[0][ee] = fma2(w0, s2v[ee], acc2[0][ee]);
                acc2[1][ee] = fma2(w1, s2v[ee], acc2[1][ee]);
                acc2[2][ee] = fma2(w2, s2v[ee], acc2[2][ee]);
            }
        }
    }
    // ---- store ACC: thread owns e = ng*8+q; per instr a half-warp group writes
    // two 64B contiguous chunks (mg 0..15 consecutive), same as before.
#pragma unroll
    for (int q = 0; q < 8; q++) {
        int idx = e_base + ng * 8 + q;
        float* op = g_ACC + (size_t)idx * 96 + mg;
#pragma unroll
        for (int p = 0; p < 3; p++) {
            float lo, hi;
            unpack2(acc2[p][q], lo, hi);
            op[16 * (2 * p)]     = lo;
            op[16 * (2 * p + 1)] = hi;
        }
    }
}

// ---------------- layer-1 fused gather+update: warp per (node, c) ----------------
// 128-thread blocks; gather at entry (overlaps cw staging); node-major mapping.
// dyn smem: 4*1056*4 = 16896 B; static SH 4*384*4 = 6144 B.
__global__ __launch_bounds__(128) void k_upd1(const float* __restrict__ ws_w,
                                              const float* __restrict__ cwg,
                                              const float* __restrict__ mwg,
                                              float* __restrict__ out) {
    extern __shared__ float dsm[];
    __shared__ __align__(16) float SH[4][384];
    int warp = threadIdx.x >> 5, lane = threadIdx.x & 31;
    float* ww = dsm + warp * 1056;
    int wg = blockIdx.x * 4 + warp;
    int node = wg / 3;
    int c = wg - node * 3;
    float* sh = SH[warp];
    int beg = g_off[node], end = g_off[node + 1];
    size_t mbase = (((size_t)3 + c) * NN + node) * 1024;
    const float* wrow = ww + lane * 33;
    const float* ws = ws_w + 288 + lane;   // l=1

    stage_w(cwg + mbase, ww, lane);        // cw staging overlaps the gather below

    if (c == 0) {
        float A0 = 0.f;
#pragma unroll 4
        for (int idx = beg; idx < end; idx++)
            A0 += __ldcs(g_ACC + (size_t)idx * 96 + lane);
        float f0 = ws[0] + ws[32] * A0 + ws[64] * A0 * A0;
        sh[lane] = g_H0[node * 32 + lane];
        __syncwarp();
        float o = 0.f;
#pragma unroll
        for (int j = 0; j < 32; j++) o += wrow[j] * sh[j];
        __syncwarp();
        stage_w(mwg + mbase, ww, lane);
        sh[lane] = f0 * A0;
        __syncwarp();
#pragma unroll
        for (int j = 0; j < 32; j++) o += wrow[j] * sh[j];
        out[(node * 32 + lane) * 13 + 0] = o;
    } else if (c == 1) {
        float A0 = 0.f, A1x = 0.f, A1y = 0.f, A1z = 0.f;
        int idx = beg;
        for (; idx + 2 <= end; idx += 2) {
            float4 ua = ((const float4*)g_US)[idx];
            float4 ub = ((const float4*)g_US)[idx + 1];
            const float* ap = g_ACC + (size_t)idx * 96 + lane;
            float a0a = __ldcs(ap),      a1a = __ldcs(ap + 32);
            float a0b = __ldcs(ap + 96), a1b = __ldcs(ap + 128);
            A0 += a0a + a0b;
            A1x += a1a * ua.x + a1b * ub.x;
            A1y += a1a * ua.y + a1b * ub.y;
            A1z += a1a * ua.z + a1b * ub.z;
        }
        if (idx < end) {
            float4 u = ((const float4*)g_US)[idx];
            const float* ap = g_ACC + (size_t)idx * 96 + lane;
            float a0 = __ldcs(ap), a1 = __ldcs(ap + 32);
            A0 += a0;
            A1x += a1 * u.x; A1y += a1 * u.y; A1z += a1 * u.z;
        }
        float f1 = ws[96] + ws[128] * A0 + ws[160] * A0 * A0;
        const float* hp = g_H1 + node * 96;
        sh[lane * 12 + 0] = hp[lane];
        sh[lane * 12 + 1] = hp[32 + lane];
        sh[lane * 12 + 2] = hp[64 + lane];
        __syncwarp();
        float o0 = 0.f, o1 = 0.f, o2 = 0.f;
#pragma unroll
        for (int j = 0; j < 32; j++) {
            float w1 = wrow[j];
            float2 hv = *(const float2*)&sh[j * 12];
            float  hz = sh[j * 12 + 2];
            o0 += w1 * hv.x; o1 += w1 * hv.y; o2 += w1 * hz;
        }
        __syncwarp();
        stage_w(mwg + mbase, ww, lane);
        sh[lane * 12 + 0] = f1 * A1x;
        sh[lane * 12 + 1] = f1 * A1y;
        sh[lane * 12 + 2] = f1 * A1z;
        __syncwarp();
#pragma unroll
        for (int j = 0; j < 32; j++) {
            float w2 = wrow[j];
            float2 mv = *(const float2*)&sh[j * 12];
            float  mz = sh[j * 12 + 2];
            o0 += w2 * mv.x; o1 += w2 * mv.y; o2 += w2 * mz;
        }
        float* op = out + (node * 32 + lane) * 13 + 1;
        op[0] = o0; op[1] = o1; op[2] = o2;
    } else {
        float A0 = 0.f;
        float A2[9] = {0.f, 0.f, 0.f, 0.f, 0.f, 0.f, 0.f, 0.f, 0.f};
        int idx = beg;
        for (; idx + 2 <= end; idx += 2) {
            float4 ua = ((const float4*)g_US)[idx];
            float4 ub = ((const float4*)g_US)[idx + 1];
            const float* ap = g_ACC + (size_t)idx * 96 + lane;
            float a0a = __ldcs(ap),      a2a = __ldcs(ap + 64);
            float a0b = __ldcs(ap + 96), a2b = __ldcs(ap + 160);
            A0 += a0a + a0b;
            float c0 = a2a * ua.x, c1 = a2a * ua.y, c2 = a2a * ua.z;
            float d0 = a2b * ub.x, d1 = a2b * ub.y, d2 = a2b * ub.z;
            A2[0] += c0 * ua.x + d0 * ub.x; A2[1] += c0 * ua.y + d0 * ub.y; A2[2] += c0 * ua.z + d0 * ub.z;
            A2[3] += c1 * ua.x + d1 * ub.x; A2[4] += c1 * ua.y + d1 * ub.y; A2[5] += c1 * ua.z + d1 * ub.z;
            A2[6] += c2 * ua.x + d2 * ub.x; A2[7] += c2 * ua.y + d2 * ub.y; A2[8] += c2 * ua.z + d2 * ub.z;
        }
        if (idx < end) {
            float4 u = ((const float4*)g_US)[idx];
            const float* ap = g_ACC + (size_t)idx * 96 + lane;
            float a0 = __ldcs(ap), a2 = __ldcs(ap + 64);
            A0 += a0;
            float b0 = a2 * u.x, b1 = a2 * u.y, b2 = a2 * u.z;
            A2[0] += b0 * u.x; A2[1] += b0 * u.y; A2[2] += b0 * u.z;
            A2[3] += b1 * u.x; A2[4] += b1 * u.y; A2[5] += b1 * u.z;
            A2[6] += b2 * u.x; A2[7] += b2 * u.y; A2[8] += b2 * u.z;
        }
        float f2 = ws[192] + ws[224] * A0 + ws[256] * A0 * A0;
        const float* hp = g_H2 + node * 288;
#pragma unroll
        for (int d = 0; d < 9; d++) sh[lane * 12 + d] = hp[d * 32 + lane];
        __syncwarp();
        float o[9];
#pragma unroll
        for (int d = 0; d < 9; d++) o[d] = 0.f;
#pragma unroll
        for (int j = 0; j < 32; j++) {
            float w1 = wrow[j];
            float4 ha = *(const float4*)&sh[j * 12];
            float4 hb = *(const float4*)&sh[j * 12 + 4];
            float  hc = sh[j * 12 + 8];
            o[0] += w1 * ha.x; o[1] += w1 * ha.y; o[2] += w1 * ha.z; o[3] += w1 * ha.w;
            o[4] += w1 * hb.x; o[5] += w1 * hb.y; o[6] += w1 * hb.z; o[7] += w1 * hb.w;
            o[8] += w1 * hc;
        }
        __syncwarp();
        stage_w(mwg + mbase, ww, lane);
#pragma unroll
        for (int d = 0; d < 9; d++) sh[lane * 12 + d] = f2 * A2[d];
        __syncwarp();
#pragma unroll
        for (int j = 0; j < 32; j++) {
            float w2 = wrow[j];
            float4 ma = *(const float4*)&sh[j * 12];
            float4 mb = *(const float4*)&sh[j * 12 + 4];
            float  mc = sh[j * 12 + 8];
            o[0] += w2 * ma.x; o[1] += w2 * ma.y; o[2] += w2 * ma.z; o[3] += w2 * ma.w;
            o[4] += w2 * mb.x; o[5] += w2 * mb.y; o[6] += w2 * mb.z; o[7] += w2 * mb.w;
            o[8] += w2 * mc;
        }
        float* op = out + (node * 32 + lane) * 13 + 4;
#pragma unroll
        for (int d = 0; d < 9; d++) op[d] = o[d];
    }
}

extern "C" void kernel_launch(void* const* d_in, const int* in_sizes, int n_in,
                              void* d_out, int out_size) {
    (void)in_sizes; (void)n_in; (void)out_size;
    const float* pos   = (const float*)d_in[0];
    const int*   ei    = (const int*)d_in[1];
    const int*   atoms = (const int*)d_in[2];
    const float* emb   = (const float*)d_in[3];
    const float* W_ab  = (const float*)d_in[4];
    const float* ws_w  = (const float*)d_in[5];
    const float* cw    = (const float*)d_in[6];
    const float* mw    = (const float*)d_in[7];
    float* out = (float*)d_out;

    const int EDGE_SMEM = (9216 + 3 * 4224) * 4;       // 87552 B
    const int UPD_SMEM  = 4 * 1056 * 4;                // 16896 B (4-warp blocks)
    cudaFuncSetAttribute(k_edge, cudaFuncAttributeMaxDynamicSharedMemorySize, EDGE_SMEM);
    cudaFuncSetAttribute(k_upd0, cudaFuncAttributeMaxDynamicSharedMemorySize, UPD_SMEM);
    cudaFuncSetAttribute(k_upd1, cudaFuncAttributeMaxDynamicSharedMemorySize, UPD_SMEM);

    k_init<<<1250, 256>>>(emb, atoms, W_ab, ei);
    k_scan<<<1, 1024>>>();
    k_fill<<<625, 256>>>(ei, pos);

    // layer 0 (edge phase analytic; gather fused into update)
    k_upd0<<<3 * NN / 4, 128, UPD_SMEM>>>(ws_w, cw, mw);
    // layer 1 (gather fused into update)
    k_edge<<<NE / 128, 256, EDGE_SMEM>>>(W_ab);
    k_upd1<<<3 * NN / 4, 128, UPD_SMEM>>>(ws_w, cw, mw, out);
}